// round 5
// baseline (speedup 1.0000x reference)
#include <cuda_runtime.h>

// Problem constants (fixed by the reference setup)
#define DE   200          // entity / output dim
#define DR   200          // relation dim
#define DIN  400          // DE + DR
#define NB   4            // num bases
#define KTOT (NB * DIN)   // 1600 rows of the collapsed matvec
#define KCH  11           // k-rows per block (148*11 = 1628 >= 1600)

#define MAXM 4096         // matched-edge capacity (expected ~8)
#define NBLK 148          // <= SM count -> whole grid resident in wave 1
#define NTHR 512

// persistent scratch (static device globals — no allocation).
// g_count/g_done are reset to 0 at the end of every launch (block 0 tail).
__device__ int      g_count;
__device__ int      g_done;
__device__ int      g_nid[MAXM];
__device__ int      g_ri[MAXM];
__device__ float4   g_att[MAXM];
__device__ unsigned g_bar_count;
__device__ unsigned g_bar_sense;

__global__ void __launch_bounds__(NTHR, 1)
fused_kernel(const float* __restrict__ ent,
             const float* __restrict__ relemb,
             const float* __restrict__ basis,
             const float* __restrict__ att,
             const int*   __restrict__ node_id,
             const int*   __restrict__ edge_src,
             const int*   __restrict__ edge_dst,
             const int*   __restrict__ edge_type,
             const int*   __restrict__ rel_index,
             const int*   __restrict__ u_ptr,
             float* __restrict__ out,
             int E) {
    const int tid = threadIdx.x;
    const int gt  = blockIdx.x * NTHR + tid;
    const int GT  = NBLK * NTHR;

    __shared__ float sy[KCH + 1];

    // ── Pre-barrier prefetch: this block's basis chunk into registers.
    //    Independent of the scan -> overlaps its DRAM latency with scanning. ──
    const int k0   = blockIdx.x * KCH;
    const int kmax = (KTOT - k0) < KCH ? (KTOT - k0) : KCH;   // may be <= 0
    const int g    = tid >> 8;          // 0 or 1
    const int o    = tid & 255;         // output index within half
    float breg[6];
    if (o < DE) {
        #pragma unroll
        for (int j = 0; j < 6; j++) {
            int kk = g * 6 + j;
            breg[j] = (kk < kmax) ? __ldcg(&basis[(size_t)(k0 + kk) * DE + o]) : 0.0f;
        }
    }

    // block 0 zeros the output accumulator (REDG target) pre-barrier
    if (blockIdx.x == 0 && tid < DE) out[tid] = 0.0f;

    // ── Phase 1: scan edge_dst; finder resolves the pointer chain so its
    //    latency overlaps with the rest of the scan + barrier wait. ──
    auto found = [&](int e) {
        int p = atomicAdd(&g_count, 1);
        if (p < MAXM) {
            int s  = __ldcg(&edge_src[e]);
            int ri = __ldcg(&rel_index[e]);
            int ty = __ldcg(&edge_type[e]);
            g_nid[p] = __ldcg(&node_id[s]);
            g_ri[p]  = ri;
            g_att[p] = __ldcg((const float4*)(att + (size_t)ty * NB));
        }
    };
    {
        const int u  = __ldcg(u_ptr);
        const int nv = E >> 2;
        const int4* ed4 = (const int4*)edge_dst;
        // 2-wide manual MLP: both int4 loads issue before either compare
        for (int i = gt; i < nv; i += 2 * GT) {
            int  i2 = i + GT;
            bool h2 = i2 < nv;
            int4 v1 = __ldcg(&ed4[i]);
            int4 v2;
            if (h2) v2 = __ldcg(&ed4[i2]);
            int b1 = i << 2;
            if (v1.x == u) found(b1 + 0);
            if (v1.y == u) found(b1 + 1);
            if (v1.z == u) found(b1 + 2);
            if (v1.w == u) found(b1 + 3);
            if (h2) {
                int b2 = i2 << 2;
                if (v2.x == u) found(b2 + 0);
                if (v2.y == u) found(b2 + 1);
                if (v2.z == u) found(b2 + 2);
                if (v2.w == u) found(b2 + 3);
            }
        }
        for (int e = (nv << 2) + gt; e < E; e += GT) {    // scalar tail
            if (__ldcg(&edge_dst[e]) == u) found(e);
        }
    }

    // ── Grid barrier (CG-style: bar.sync, tid0 fence + arrive/spin) ──
    __syncthreads();
    if (tid == 0) {
        __threadfence();                       // publish this block's stores
        volatile unsigned* sense = &g_bar_sense;
        unsigned s = *sense;
        unsigned a = atomicAdd(&g_bar_count, 1u);
        if (a == NBLK - 1) {
            g_bar_count = 0;                   // reset for next launch
            __threadfence();
            atomicAdd(&g_bar_sense, 1u);       // release
        } else {
            while (*sense == s) { }
        }
        __threadfence();                       // acquire
    }
    __syncthreads();

    // ── Phase 2: y[k] = sum_m att[m][k/DIN] * xj_m[k%DIN] for this block's
    //    k-rows, then out[o] += inv * sum_k y[k] * basis[k,o] via REDG. ──
    const int   cnt  = __ldcg(&g_count);
    const int   cntc = cnt < MAXM ? cnt : MAXM;
    const float inv  = 1.0f / fmaxf((float)cnt, 1.0f);

    if (tid < KCH) sy[tid] = 0.0f;
    __syncthreads();

    if (kmax > 0 && cntc > 0) {
        const int total = kmax * cntc;
        for (int p = tid; p < total; p += NTHR) {
            int kk = p / cntc;
            int m  = p - kk * cntc;
            int k  = k0 + kk;
            int b  = k / DIN;
            int i  = k - b * DIN;
            float x = (i < DE)
                ? __ldcg(&ent[(size_t)g_nid[m] * DE + i])
                : __ldcg(&relemb[(size_t)g_ri[m] * DR + (i - DE)]);
            float a = ((const float*)&g_att[m])[b];
            atomicAdd(&sy[kk], a * x);
        }
    }
    __syncthreads();

    if (kmax > 0 && cntc > 0 && o < DE) {
        float acc = 0.0f;
        #pragma unroll
        for (int j = 0; j < 6; j++) {
            int kk = g * 6 + j;
            if (kk < kmax) acc += sy[kk] * breg[j];
        }
        atomicAdd(&out[o], acc * inv);    // fire-and-forget REDG, pre-scaled
    }

    // ── Tail: done counter exists only to reset g_count deterministically ──
    __syncthreads();
    if (tid == 0) {
        __threadfence();
        atomicAdd(&g_done, 1);
        if (blockIdx.x == 0) {
            while (*(volatile int*)&g_done != NBLK) { }
            g_count = 0;
            g_done  = 0;
        }
    }
}

extern "C" void kernel_launch(void* const* d_in, const int* in_sizes, int n_in,
                              void* d_out, int out_size) {
    const float* ent    = (const float*)d_in[0];  // [100000, 200]
    const float* relemb = (const float*)d_in[1];  // [200, 200]
    const float* basis  = (const float*)d_in[2];  // [4, 400, 200]
    const float* att    = (const float*)d_in[3];  // [400, 4]
    const int* node_id  = (const int*)d_in[4];    // [50000]
    const int* edge_src = (const int*)d_in[5];    // [400000]
    const int* edge_dst = (const int*)d_in[6];    // [400000]
    const int* edge_typ = (const int*)d_in[7];    // [400000]
    const int* rel_idx  = (const int*)d_in[8];    // [400000]
    const int* u_ptr    = (const int*)d_in[9];    // scalar
    float* out = (float*)d_out;                   // [200]

    int E = in_sizes[6];

    fused_kernel<<<NBLK, NTHR>>>(ent, relemb, basis, att,
                                 node_id, edge_src, edge_dst, edge_typ, rel_idx,
                                 u_ptr, out, E);
}

// round 6
// speedup vs baseline: 1.2179x; 1.2179x over previous
#include <cuda_runtime.h>

// Problem constants (fixed by the reference setup)
#define DE   200          // entity / output dim
#define DR   200          // relation dim
#define DIN  400          // DE + DR
#define NB   4            // num bases
#define KTOT (NB * DIN)   // 1600 rows of the collapsed matvec

#define MAXM 4096         // matched-edge capacity (expected ~8)
#define NBLK 148          // <= SM count -> whole grid resident in wave 1
#define NTHR 512
#define NMM  37           // blocks that own the matvec
#define KCH  44           // k-rows per matvec block (37*44 = 1628 >= 1600)
#define KPG  22           // k-rows per thread-group (2 groups of 200 o-threads)

// persistent scratch (static device globals — no allocation).
// g_count/g_done are reset to 0 by the LAST block to finish (no spin).
__device__ int      g_count;
__device__ int      g_done;
__device__ int      g_nid[MAXM];
__device__ int      g_ri[MAXM];
__device__ float4   g_att[MAXM];
__device__ unsigned g_bar_count;
__device__ unsigned g_bar_sense;

__global__ void __launch_bounds__(NTHR, 1)
fused_kernel(const float* __restrict__ ent,
             const float* __restrict__ relemb,
             const float* __restrict__ basis,
             const float* __restrict__ att,
             const int*   __restrict__ node_id,
             const int*   __restrict__ edge_src,
             const int*   __restrict__ edge_dst,
             const int*   __restrict__ edge_type,
             const int*   __restrict__ rel_index,
             const int*   __restrict__ u_ptr,
             float* __restrict__ out,
             int E) {
    const int tid = threadIdx.x;
    const int gt  = blockIdx.x * NTHR + tid;
    const int GT  = NBLK * NTHR;

    const bool is_mv = (blockIdx.x < NMM);
    const int  k0    = blockIdx.x * KCH;
    const int  kmax  = is_mv ? ((KTOT - k0) < KCH ? (KTOT - k0) : KCH) : 0;
    const int  g     = tid >> 8;     // thread-group 0/1
    const int  o     = tid & 255;    // output index within group (valid if < DE)

    __shared__ int   scnt;
    __shared__ float sy[KCH];
    __shared__ float s1[DE];

    // ── Pre-barrier: matvec blocks prefetch their whole basis chunk into
    //    registers (22 floats/thread); overlaps with the scan below. ──
    float breg[KPG];
    if (is_mv && o < DE) {
        #pragma unroll
        for (int j = 0; j < KPG; j++) {
            int kk = g * KPG + j;
            breg[j] = (kk < kmax) ? __ldcg(&basis[(size_t)(k0 + kk) * DE + o]) : 0.0f;
        }
    }
    // block 0 zeros the output (REDG target) pre-barrier
    if (blockIdx.x == 0 && tid < DE) out[tid] = 0.0f;

    // ── Phase 1: scan edge_dst; the finder resolves the pointer chain so
    //    its latency overlaps the rest of the scan + barrier wait. ──
    auto found = [&](int e) {
        int p = atomicAdd(&g_count, 1);
        if (p < MAXM) {
            int s  = __ldcg(&edge_src[e]);
            int ri = __ldcg(&rel_index[e]);
            int ty = __ldcg(&edge_type[e]);
            g_nid[p] = __ldcg(&node_id[s]);
            g_ri[p]  = ri;
            g_att[p] = __ldcg((const float4*)(att + (size_t)ty * NB));
        }
    };
    {
        const int u  = *u_ptr;          // L1-cached broadcast (NOT .cg)
        const int nv = E >> 2;
        const int4* ed4 = (const int4*)edge_dst;
        for (int i = gt; i < nv; i += 2 * GT) {   // 2-wide MLP
            int  i2 = i + GT;
            bool h2 = i2 < nv;
            int4 v1 = __ldcg(&ed4[i]);
            int4 v2;
            if (h2) v2 = __ldcg(&ed4[i2]);
            int b1 = i << 2;
            if (v1.x == u) found(b1 + 0);
            if (v1.y == u) found(b1 + 1);
            if (v1.z == u) found(b1 + 2);
            if (v1.w == u) found(b1 + 3);
            if (h2) {
                int b2 = i2 << 2;
                if (v2.x == u) found(b2 + 0);
                if (v2.y == u) found(b2 + 1);
                if (v2.z == u) found(b2 + 2);
                if (v2.w == u) found(b2 + 3);
            }
        }
        for (int e = (nv << 2) + gt; e < E; e += GT) {   // scalar tail
            if (__ldcg(&edge_dst[e]) == u) found(e);
        }
    }

    // ── Grid barrier (CG-style: bar.sync, tid0 fence + arrive/spin) ──
    __syncthreads();
    if (tid == 0) {
        __threadfence();                       // publish this block's stores
        volatile unsigned* sense = &g_bar_sense;
        unsigned s = *sense;
        unsigned a = atomicAdd(&g_bar_count, 1u);
        if (a == NBLK - 1) {
            g_bar_count = 0;                   // reset for next launch
            __threadfence();
            atomicAdd(&g_bar_sense, 1u);       // release
        } else {
            while (*sense == s) { }
        }
        __threadfence();                       // acquire
    }
    // tid0 reads the count ONCE per block; everyone else gets it from smem
    if (tid == 0) scnt = *(volatile int*)&g_count;
    if (tid < KCH) sy[tid] = 0.0f;
    __syncthreads();

    const int   cnt  = scnt;
    const int   cntc = cnt < MAXM ? cnt : MAXM;
    const float inv  = 1.0f / fmaxf((float)cnt, 1.0f);

    // ── Phase 2 (matvec blocks only):
    //    y[k] = sum_m att[m][k/DIN] * xj_m[k%DIN] for this block's k-rows ──
    if (is_mv && cntc > 0) {
        const int total = kmax * cntc;
        for (int p = tid; p < total; p += NTHR) {
            int kk = p / cntc;
            int m  = p - kk * cntc;
            int k  = k0 + kk;
            int b  = k / DIN;
            int i  = k - b * DIN;
            float x = (i < DE)
                ? __ldcg(&ent[(size_t)__ldcg(&g_nid[m]) * DE + i])
                : __ldcg(&relemb[(size_t)__ldcg(&g_ri[m]) * DR + (i - DE)]);
            float a = __ldcg(((const float*)&g_att[m]) + b);
            atomicAdd(&sy[kk], a * x);
        }
    }
    __syncthreads();

    // out[o] += inv * sum_kk y[kk]*basis[k0+kk,o]; group-1 partial goes
    // through smem so each matvec block issues ONE REDG lane per output.
    float acc = 0.0f;
    if (is_mv && cntc > 0 && o < DE) {
        #pragma unroll
        for (int j = 0; j < KPG; j++) acc += sy[g * KPG + j] * breg[j];
        if (g == 1) s1[o] = acc;
    }
    __syncthreads();
    if (is_mv && cntc > 0 && o < DE && g == 0) {
        atomicAdd(&out[o], (acc + s1[o]) * inv);   // fire-and-forget REDG
    }

    // ── Tail: last block to arrive resets scratch (no spin) ──
    __syncthreads();
    if (tid == 0) {
        __threadfence();
        int a = atomicAdd(&g_done, 1);
        if (a == NBLK - 1) { g_count = 0; g_done = 0; }
    }
}

extern "C" void kernel_launch(void* const* d_in, const int* in_sizes, int n_in,
                              void* d_out, int out_size) {
    const float* ent    = (const float*)d_in[0];  // [100000, 200]
    const float* relemb = (const float*)d_in[1];  // [200, 200]
    const float* basis  = (const float*)d_in[2];  // [4, 400, 200]
    const float* att    = (const float*)d_in[3];  // [400, 4]
    const int* node_id  = (const int*)d_in[4];    // [50000]
    const int* edge_src = (const int*)d_in[5];    // [400000]
    const int* edge_dst = (const int*)d_in[6];    // [400000]
    const int* edge_typ = (const int*)d_in[7];    // [400000]
    const int* rel_idx  = (const int*)d_in[8];    // [400000]
    const int* u_ptr    = (const int*)d_in[9];    // scalar
    float* out = (float*)d_out;                   // [200]

    int E = in_sizes[6];

    fused_kernel<<<NBLK, NTHR>>>(ent, relemb, basis, att,
                                 node_id, edge_src, edge_dst, edge_typ, rel_idx,
                                 u_ptr, out, E);
}